// round 14
// baseline (speedup 1.0000x reference)
#include <cuda_runtime.h>
#include <cuda_fp16.h>
#include <cstdint>

#define D_DIM   1024
#define NKB     64            // 1024/16 k-blocks
#define NITER   32            // 1024/32
#define STAGES  4
#define BM      128
#define BN      128
#define NPA     64            // 8192/128 row panels
#define NPB     32            // 4096/128 col panels

#define A_KB_BYTES 4096
#define B_KB_BYTES 4096
#define STAGE_BYTES 16384
#define SMEM_DYN (1024 + STAGES * STAGE_BYTES)
#define DELTA 5e-3f

__device__ __align__(128) unsigned char g_A[(size_t)NPA * NKB * A_KB_BYTES]; // 16.8 MB
__device__ __align__(128) unsigned char g_B[(size_t)NPB * NKB * B_KB_BYTES]; // 8.4 MB
__device__ unsigned long long g_cands[(size_t)8192 * 256];                    // 16 MB
__device__ float g_einv[8192];
__device__ float g_cinv[4096];
__device__ int g_cntDone[NPA];

struct __align__(8) H4 { __half2 a, b; };

// ---------------- PTX helpers ----------------
__device__ __forceinline__ uint32_t smem_u32(const void* p) {
    uint32_t a;
    asm("{ .reg .u64 t; cvta.to.shared.u64 t, %1; cvt.u32.u64 %0, t; }" : "=r"(a) : "l"(p));
    return a;
}
#define MBAR_INIT(a, n) \
    asm volatile("mbarrier.init.shared.b64 [%0], %1;" :: "r"(a), "r"((uint32_t)(n)) : "memory")
#define MBAR_ARRIVE(a) \
    asm volatile("mbarrier.arrive.shared.b64 _, [%0];" :: "r"(a) : "memory")
#define MBAR_EXPECT_TX(a, b) \
    asm volatile("mbarrier.arrive.expect_tx.shared.b64 _, [%0], %1;" :: "r"(a), "r"((uint32_t)(b)) : "memory")
#define MBAR_WAIT(a, ph) do {                                                      \
    uint32_t _m = (a), _p = (ph), _d;                                              \
    asm volatile("{ .reg .pred p; mbarrier.try_wait.parity.acquire.cta.shared::cta.b64 p, [%1], %2; selp.b32 %0,1,0,p; }" \
        : "=r"(_d) : "r"(_m), "r"(_p) : "memory");                                 \
    if (!_d) {                                                                     \
        asm volatile("{ .reg .pred P; L1_%=: mbarrier.try_wait.parity.acquire.cta.shared::cta.b64 P, [%0], %1, 0x989680; @P bra.uni L2_%=; bra.uni L1_%=; L2_%=: }" \
            :: "r"(_m), "r"(_p) : "memory");                                       \
    }                                                                              \
} while (0)

__device__ __forceinline__ void bulk_g2s(uint32_t dst, const void* src,
                                         uint32_t bytes, uint32_t mbar) {
    asm volatile("cp.async.bulk.shared::cluster.global.mbarrier::complete_tx::bytes [%0], [%1], %2, [%3];"
        :: "r"(dst), "l"(src), "r"(bytes), "r"(mbar) : "memory");
}
__device__ __forceinline__ void hmma16(uint32_t* d, const uint32_t* a, const uint32_t* b) {
    asm volatile(
        "mma.sync.aligned.m16n8k16.row.col.f16.f16.f16.f16 "
        "{%0,%1}, {%2,%3,%4,%5}, {%6,%7}, {%0,%1};"
        : "+r"(d[0]), "+r"(d[1])
        : "r"(a[0]), "r"(a[1]), "r"(a[2]), "r"(a[3]), "r"(b[0]), "r"(b[1]));
}
__device__ __forceinline__ unsigned long long enc_key(float sim, int col) {
    return ((unsigned long long)__float_as_uint(sim) << 32) |
           (unsigned long long)(0xFFFFFFFFu - (unsigned)col);
}

// ---------------- split (R12-identical) ----------------
__global__ void __launch_bounds__(512) split_kernel(const float* __restrict__ emb,
                                                    const float* __restrict__ cen,
                                                    int B_, int C_) {
    __shared__ __align__(16) unsigned char sh[16 * 2064];
    const int t = threadIdx.x;
    const int w = t >> 5;
    const int l = t & 31;

    const int nA = B_ >> 4;
    const bool isA = (int)blockIdx.x < nA;
    const int g = isA ? blockIdx.x : blockIdx.x - nA;
    const int row = g * 16 + w;
    const float* p = (isA ? emb : cen) + (size_t)row * D_DIM;

    float4 f[8];
    float s = 0.f;
#pragma unroll
    for (int j = 0; j < 8; ++j) {
        f[j] = ((const float4*)p)[l + 32 * j];
        s += f[j].x * f[j].x + f[j].y * f[j].y + f[j].z * f[j].z + f[j].w * f[j].w;
    }
#pragma unroll
    for (int m = 16; m >= 1; m >>= 1) s += __shfl_xor_sync(0xffffffffu, s, m);
    const float inv = 1.0f / fmaxf(sqrtf(s), 1e-12f);
    if (l == 0) {
        if (isA) g_einv[row] = inv;
        else     g_cinv[row] = inv;
    }

#pragma unroll
    for (int j = 0; j < 8; ++j) {
        H4 hv;
        hv.a = __floats2half2_rn(f[j].x * inv, f[j].y * inv);
        hv.b = __floats2half2_rn(f[j].z * inv, f[j].w * inv);
        *(H4*)(sh + w * 2064 + l * 8 + 256 * j) = hv;
    }
    __syncthreads();

    if (isA) {
        const int pnl = g >> 3, mblk = g & 7;
        unsigned char* base = g_A + (size_t)pnl * NKB * A_KB_BYTES + mblk * 512 + l * 16;
#pragma unroll
        for (int it = 0; it < 4; ++it) {
            const int kb = it * 16 + w;
            uint32_t v[4];
#pragma unroll
            for (int r = 0; r < 4; ++r) {
                const int i  = (l >> 2) + 8 * (r & 1);
                const int kk = kb * 16 + (l & 3) * 2 + 8 * (r >> 1);
                v[r] = *(const uint32_t*)(sh + i * 2064 + kk * 2);
            }
            *(uint4*)(base + (size_t)kb * A_KB_BYTES) = make_uint4(v[0], v[1], v[2], v[3]);
        }
    } else {
        const int pnl = g >> 3;
        const int nb_base = (g & 7) * 2;
        unsigned char* base = g_B + (size_t)pnl * NKB * B_KB_BYTES + l * 8;
#pragma unroll
        for (int it = 0; it < 8; ++it) {
            const int ci = it * 16 + w;
            const int kb = ci >> 1, nloc = ci & 1;
            uint32_t v[2];
#pragma unroll
            for (int s2 = 0; s2 < 2; ++s2) {
                const int i  = nloc * 8 + (l >> 2);
                const int kk = kb * 16 + (l & 3) * 2 + 8 * s2;
                v[s2] = *(const uint32_t*)(sh + i * 2064 + kk * 2);
            }
            *(uint2*)(base + (size_t)kb * B_KB_BYTES + (nb_base + nloc) * 256) =
                make_uint2(v[0], v[1]);
        }
    }
}

// ---------------- HMMA GEMM (R12) + election-fused rescore ----------------
__global__ void __launch_bounds__(160, 3) gemm_kernel(
    const float* __restrict__ emb, const float* __restrict__ cen,
    float* __restrict__ out, int twoout) {
    extern __shared__ __align__(16) unsigned char smem[];
    const uint32_t sbase = smem_u32(smem);
    const int tid = threadIdx.x;
    const int wid = tid >> 5;
    const int lane = tid & 31;
    const int by = blockIdx.y, bx = blockIdx.x;

    const uint32_t mb_full  = sbase;
    const uint32_t mb_empty = sbase + 64;
    const uint32_t tiles    = sbase + 1024;

    if (tid == 0) {
#pragma unroll
        for (int s = 0; s < STAGES; ++s) {
            MBAR_INIT(mb_full + s * 8, 1);
            MBAR_INIT(mb_empty + s * 8, 4);     // 4 consumer warps
        }
    }
    __syncthreads();

    if (wid == 4) {
        if (lane == 0) {
            const unsigned char* aP = g_A + (size_t)by * NKB * A_KB_BYTES;
            const unsigned char* bP = g_B + (size_t)bx * NKB * B_KB_BYTES;
            for (int kt = 0; kt < NITER; ++kt) {
                const int s = kt & (STAGES - 1);
                MBAR_WAIT(mb_empty + s * 8, 1u ^ ((kt >> 2) & 1));
                MBAR_EXPECT_TX(mb_full + s * 8, STAGE_BYTES);
                const uint32_t st = tiles + s * STAGE_BYTES;
                bulk_g2s(st,        aP + (size_t)(2 * kt) * A_KB_BYTES, 2 * A_KB_BYTES,
                         mb_full + s * 8);
                bulk_g2s(st + 8192, bP + (size_t)(2 * kt) * B_KB_BYTES, 2 * B_KB_BYTES,
                         mb_full + s * 8);
            }
        }
        return;   // producer exits; rescore uses only the 4 compute warps
    }

    const int wm = wid & 1;      // M half (64 rows)
    const int wn = wid >> 1;     // N half (64 cols)

    uint32_t acc[4][8][2];
#pragma unroll
    for (int mi = 0; mi < 4; ++mi)
#pragma unroll
        for (int ni = 0; ni < 8; ++ni) { acc[mi][ni][0] = 0u; acc[mi][ni][1] = 0u; }

    const uint32_t aoff = lane * 16;
    const uint32_t boff = lane * 8;

    for (int kt = 0; kt < NITER; ++kt) {
        const int s = kt & (STAGES - 1);
        MBAR_WAIT(mb_full + s * 8, (kt >> 2) & 1);
        const uint32_t stA = tiles + s * STAGE_BYTES;
        const uint32_t stB = stA + 8192;
#pragma unroll
        for (int s16 = 0; s16 < 2; ++s16) {
            uint32_t a[4][4], b[8][2];
#pragma unroll
            for (int mi = 0; mi < 4; ++mi) {
                const uint32_t ad = stA + (uint32_t)(s16 * 8 + wm * 4 + mi) * 512 + aoff;
                asm volatile("ld.shared.v4.b32 {%0,%1,%2,%3}, [%4];"
                    : "=r"(a[mi][0]), "=r"(a[mi][1]), "=r"(a[mi][2]), "=r"(a[mi][3])
                    : "r"(ad));
            }
#pragma unroll
            for (int ni = 0; ni < 8; ++ni) {
                const uint32_t bd = stB + (uint32_t)(s16 * 16 + wn * 8 + ni) * 256 + boff;
                asm volatile("ld.shared.v2.b32 {%0,%1}, [%2];"
                    : "=r"(b[ni][0]), "=r"(b[ni][1]) : "r"(bd));
            }
#pragma unroll
            for (int mi = 0; mi < 4; ++mi)
#pragma unroll
                for (int ni = 0; ni < 8; ++ni)
                    hmma16(acc[mi][ni], a[mi], b[ni]);
        }
        if (lane == 0) MBAR_ARRIVE(mb_empty + s * 8);
    }

    // ---- epilogue: clip, top-2 per (row, 32-col quarter); warp owns 2 quarters ----
    const int rowbase = by * BM + wm * 64;
#pragma unroll
    for (int mi = 0; mi < 4; ++mi) {
#pragma unroll
        for (int ih = 0; ih < 2; ++ih) {
            const int r = rowbase + mi * 16 + ih * 8 + (lane >> 2);
#pragma unroll
            for (int g4 = 0; g4 < 2; ++g4) {
                const int colbase = bx * BN + wn * 64 + g4 * 32 + (lane & 3) * 2;
                unsigned long long k1 = 0ULL, k2 = 0ULL;
#pragma unroll
                for (int n4 = 0; n4 < 4; ++n4) {
                    const int ni = g4 * 4 + n4;
                    const __half2 hv = *(__half2*)&acc[mi][ni][ih];
                    const float s0 = fminf(fmaxf(__low2float(hv), 0.f), 1.f);
                    const float s1 = fminf(fmaxf(__high2float(hv), 0.f), 1.f);
                    const int c = colbase + n4 * 8;
                    unsigned long long key = enc_key(s0, c);
                    if (key > k1) { k2 = k1; k1 = key; }
                    else if (key > k2) { k2 = key; }
                    key = enc_key(s1, c + 1);
                    if (key > k1) { k2 = k1; k1 = key; }
                    else if (key > k2) { k2 = key; }
                }
#pragma unroll
                for (int m = 1; m <= 2; m <<= 1) {
                    const unsigned long long o1 = __shfl_xor_sync(0xffffffffu, k1, m);
                    const unsigned long long o2 = __shfl_xor_sync(0xffffffffu, k2, m);
                    if (o1 > k1) { k2 = (k1 > o2) ? k1 : o2; k1 = o1; }
                    else         { k2 = (k2 > o1) ? k2 : o1; }
                }
                if ((lane & 3) == 0) {
                    ulonglong2 kk; kk.x = k1; kk.y = k2;
                    *(ulonglong2*)&g_cands[(size_t)r * 256 + bx * 8 +
                                           (wn * 2 + g4) * 2] = kk;
                }
            }
        }
    }

    // ---- election: last CTA of this row panel rescores it ----
    __shared__ int s_last;
    asm volatile("bar.sync 1, 128;" ::: "memory");   // 4 compute warps only
    if (tid == 0) {
        __threadfence();
        s_last = (atomicAdd(&g_cntDone[by], 1) == NPB - 1) ? 1 : 0;
    }
    asm volatile("bar.sync 1, 128;" ::: "memory");
    if (!s_last) return;
    __threadfence();
    if (tid == 0) g_cntDone[by] = 0;   // self-reset for graph replay

    // rescore 128 rows with 4 warps (32 rows each); warp-local only
    __shared__ unsigned long long list[4][16];
    __shared__ int lcnt[4];

    for (int rr = 0; rr < 32; ++rr) {
        const int row = by * BM + wid * 32 + rr;

        unsigned long long k[8];
#pragma unroll
        for (int j = 0; j < 8; ++j)
            k[j] = g_cands[(size_t)row * 256 + j * 32 + lane];

        unsigned long long kmax = 0ULL;
#pragma unroll
        for (int j = 0; j < 8; ++j) if (k[j] > kmax) kmax = k[j];
#pragma unroll
        for (int m = 16; m >= 1; m >>= 1) {
            const unsigned long long o = __shfl_xor_sync(0xffffffffu, kmax, m);
            if (o > kmax) kmax = o;
        }
        const float smax = __uint_as_float((unsigned)(kmax >> 32));
        const float th = smax - DELTA;

        if (lane == 0) lcnt[wid] = 0;
        __syncwarp();
#pragma unroll
        for (int j = 0; j < 8; ++j) {
            if (__uint_as_float((unsigned)(k[j] >> 32)) >= th) {
                const int pos = atomicAdd(&lcnt[wid], 1);
                if (pos < 16) list[wid][pos] = k[j];
            }
        }
        __syncwarp();
        const int n = min(lcnt[wid], 16);

        const float4* e4 = (const float4*)(emb + (size_t)row * D_DIM);
        const float einv = g_einv[row];

        unsigned long long bestk = 0ULL;
        for (int i = 0; i < n; ++i) {
            const unsigned col = 0xFFFFFFFFu - (unsigned)(list[wid][i] & 0xFFFFFFFFu);
            const float4* c4 = (const float4*)(cen + (size_t)col * D_DIM);
            float d = 0.f;
#pragma unroll
            for (int t2 = 0; t2 < 8; ++t2) {
                const float4 ev = e4[t2 * 32 + lane];
                const float4 cv = c4[t2 * 32 + lane];
                d += ev.x * cv.x + ev.y * cv.y + ev.z * cv.z + ev.w * cv.w;
            }
#pragma unroll
            for (int m = 16; m >= 1; m >>= 1) d += __shfl_xor_sync(0xffffffffu, d, m);
            const float sim = fminf(fmaxf(d * einv * g_cinv[col], 0.f), 1.f);
            const unsigned long long key = enc_key(sim, (int)col);
            if (key > bestk) bestk = key;
        }

        if (lane == 0) {
            const float bsim = __uint_as_float((unsigned)(bestk >> 32));
            const unsigned bcol = 0xFFFFFFFFu - (unsigned)(bestk & 0xFFFFFFFFu);
            float nov = sqrtf(fmaxf(1.0f - bsim, 0.0f));
            out[row] = fminf(fmaxf(nov, 0.0f), 1.0f);
            if (twoout) out[8192 + row] = (float)bcol;
        }
    }
}

// ---------------- launch ----------------
extern "C" void kernel_launch(void* const* d_in, const int* in_sizes, int n_in,
                              void* d_out, int out_size) {
    const float* emb = (const float*)d_in[0];
    const float* cen = (const float*)d_in[1];
    const int B_ = in_sizes[0] / D_DIM;   // 8192
    const int C_ = in_sizes[1] / D_DIM;   // 4096

    split_kernel<<<(B_ + C_) / 16, 512>>>(emb, cen, B_, C_);

    cudaFuncSetAttribute(gemm_kernel,
                         cudaFuncAttributeMaxDynamicSharedMemorySize, SMEM_DYN);
    const int twoout = (out_size >= 2 * B_) ? 1 : 0;
    dim3 grid(C_ / BN, B_ / BM);          // 32 x 64 = 2048 CTAs
    gemm_kernel<<<grid, 160, SMEM_DYN>>>(emb, cen, (float*)d_out, twoout);
}

// round 15
// speedup vs baseline: 1.2773x; 1.2773x over previous
#include <cuda_runtime.h>
#include <cuda_fp16.h>
#include <cstdint>

#define D_DIM   1024
#define NKB     64            // 1024/16 k-blocks
#define NITER   32            // 1024/32
#define STAGES  6
#define BM      128
#define BN      128
#define NPA     64            // 8192/128 row panels
#define NPB     32            // 4096/128 col panels

#define A_KB_BYTES 4096
#define B_KB_BYTES 4096
#define STAGE_BYTES 16384
#define SMEM_DYN (1024 + STAGES * STAGE_BYTES)   // 99328 -> 2 CTAs/SM
#define DELTA 5e-3f

__device__ __align__(128) unsigned char g_A[(size_t)NPA * NKB * A_KB_BYTES]; // 16.8 MB
__device__ __align__(128) unsigned char g_B[(size_t)NPB * NKB * B_KB_BYTES]; // 8.4 MB
__device__ unsigned long long g_cands[(size_t)8192 * 256];                    // 16 MB
__device__ float g_einv[8192];
__device__ float g_cinv[4096];

struct __align__(8) H4 { __half2 a, b; };

// ---------------- PTX helpers ----------------
__device__ __forceinline__ uint32_t smem_u32(const void* p) {
    uint32_t a;
    asm("{ .reg .u64 t; cvta.to.shared.u64 t, %1; cvt.u32.u64 %0, t; }" : "=r"(a) : "l"(p));
    return a;
}
#define MBAR_INIT(a, n) \
    asm volatile("mbarrier.init.shared.b64 [%0], %1;" :: "r"(a), "r"((uint32_t)(n)) : "memory")
#define MBAR_ARRIVE(a) \
    asm volatile("mbarrier.arrive.shared.b64 _, [%0];" :: "r"(a) : "memory")
#define MBAR_EXPECT_TX(a, b) \
    asm volatile("mbarrier.arrive.expect_tx.shared.b64 _, [%0], %1;" :: "r"(a), "r"((uint32_t)(b)) : "memory")
#define MBAR_WAIT(a, ph) do {                                                      \
    uint32_t _m = (a), _p = (ph), _d;                                              \
    asm volatile("{ .reg .pred p; mbarrier.try_wait.parity.acquire.cta.shared::cta.b64 p, [%1], %2; selp.b32 %0,1,0,p; }" \
        : "=r"(_d) : "r"(_m), "r"(_p) : "memory");                                 \
    if (!_d) {                                                                     \
        asm volatile("{ .reg .pred P; L1_%=: mbarrier.try_wait.parity.acquire.cta.shared::cta.b64 P, [%0], %1, 0x989680; @P bra.uni L2_%=; bra.uni L1_%=; L2_%=: }" \
            :: "r"(_m), "r"(_p) : "memory");                                       \
    }                                                                              \
} while (0)

__device__ __forceinline__ void bulk_g2s(uint32_t dst, const void* src,
                                         uint32_t bytes, uint32_t mbar) {
    asm volatile("cp.async.bulk.shared::cluster.global.mbarrier::complete_tx::bytes [%0], [%1], %2, [%3];"
        :: "r"(dst), "l"(src), "r"(bytes), "r"(mbar) : "memory");
}
__device__ __forceinline__ void hmma16(uint32_t* d, const uint32_t* a, const uint32_t* b) {
    asm volatile(
        "mma.sync.aligned.m16n8k16.row.col.f16.f16.f16.f16 "
        "{%0,%1}, {%2,%3,%4,%5}, {%6,%7}, {%0,%1};"
        : "+r"(d[0]), "+r"(d[1])
        : "r"(a[0]), "r"(a[1]), "r"(a[2]), "r"(a[3]), "r"(b[0]), "r"(b[1]));
}
__device__ __forceinline__ unsigned long long enc_key(float sim, int col) {
    return ((unsigned long long)__float_as_uint(sim) << 32) |
           (unsigned long long)(0xFFFFFFFFu - (unsigned)col);
}

// ---------------- split (R12-identical) ----------------
__global__ void __launch_bounds__(512) split_kernel(const float* __restrict__ emb,
                                                    const float* __restrict__ cen,
                                                    int B_, int C_) {
    __shared__ __align__(16) unsigned char sh[16 * 2064];
    const int t = threadIdx.x;
    const int w = t >> 5;
    const int l = t & 31;

    const int nA = B_ >> 4;
    const bool isA = (int)blockIdx.x < nA;
    const int g = isA ? blockIdx.x : blockIdx.x - nA;
    const int row = g * 16 + w;
    const float* p = (isA ? emb : cen) + (size_t)row * D_DIM;

    float4 f[8];
    float s = 0.f;
#pragma unroll
    for (int j = 0; j < 8; ++j) {
        f[j] = ((const float4*)p)[l + 32 * j];
        s += f[j].x * f[j].x + f[j].y * f[j].y + f[j].z * f[j].z + f[j].w * f[j].w;
    }
#pragma unroll
    for (int m = 16; m >= 1; m >>= 1) s += __shfl_xor_sync(0xffffffffu, s, m);
    const float inv = 1.0f / fmaxf(sqrtf(s), 1e-12f);
    if (l == 0) {
        if (isA) g_einv[row] = inv;
        else     g_cinv[row] = inv;
    }

#pragma unroll
    for (int j = 0; j < 8; ++j) {
        H4 hv;
        hv.a = __floats2half2_rn(f[j].x * inv, f[j].y * inv);
        hv.b = __floats2half2_rn(f[j].z * inv, f[j].w * inv);
        *(H4*)(sh + w * 2064 + l * 8 + 256 * j) = hv;
    }
    __syncthreads();

    if (isA) {
        const int pnl = g >> 3, mblk = g & 7;
        unsigned char* base = g_A + (size_t)pnl * NKB * A_KB_BYTES + mblk * 512 + l * 16;
#pragma unroll
        for (int it = 0; it < 4; ++it) {
            const int kb = it * 16 + w;
            uint32_t v[4];
#pragma unroll
            for (int r = 0; r < 4; ++r) {
                const int i  = (l >> 2) + 8 * (r & 1);
                const int kk = kb * 16 + (l & 3) * 2 + 8 * (r >> 1);
                v[r] = *(const uint32_t*)(sh + i * 2064 + kk * 2);
            }
            *(uint4*)(base + (size_t)kb * A_KB_BYTES) = make_uint4(v[0], v[1], v[2], v[3]);
        }
    } else {
        const int pnl = g >> 3;
        const int nb_base = (g & 7) * 2;
        unsigned char* base = g_B + (size_t)pnl * NKB * B_KB_BYTES + l * 8;
#pragma unroll
        for (int it = 0; it < 8; ++it) {
            const int ci = it * 16 + w;
            const int kb = ci >> 1, nloc = ci & 1;
            uint32_t v[2];
#pragma unroll
            for (int s2 = 0; s2 < 2; ++s2) {
                const int i  = nloc * 8 + (l >> 2);
                const int kk = kb * 16 + (l & 3) * 2 + 8 * s2;
                v[s2] = *(const uint32_t*)(sh + i * 2064 + kk * 2);
            }
            *(uint2*)(base + (size_t)kb * B_KB_BYTES + (nb_base + nloc) * 256) =
                make_uint2(v[0], v[1]);
        }
    }
}

// ---------------- HMMA GEMM: 4 warps x (64x64), 6 stages, 2 CTAs/SM ----------------
__global__ void __launch_bounds__(160, 2) gemm_kernel() {
    extern __shared__ __align__(16) unsigned char smem[];
    const uint32_t sbase = smem_u32(smem);
    const int tid = threadIdx.x;
    const int wid = tid >> 5;
    const int lane = tid & 31;

    const uint32_t mb_full  = sbase;
    const uint32_t mb_empty = sbase + 64;
    const uint32_t tiles    = sbase + 1024;

    if (tid == 0) {
#pragma unroll
        for (int s = 0; s < STAGES; ++s) {
            MBAR_INIT(mb_full + s * 8, 1);
            MBAR_INIT(mb_empty + s * 8, 4);     // 4 consumer warps
        }
    }
    __syncthreads();

    if (wid == 4) {
        if (lane == 0) {
            const unsigned char* aP = g_A + (size_t)blockIdx.y * NKB * A_KB_BYTES;
            const unsigned char* bP = g_B + (size_t)blockIdx.x * NKB * B_KB_BYTES;
            int s = 0, e = 0;
            for (int kt = 0; kt < NITER; ++kt) {
                MBAR_WAIT(mb_empty + s * 8, 1 ^ e);
                MBAR_EXPECT_TX(mb_full + s * 8, STAGE_BYTES);
                const uint32_t st = tiles + s * STAGE_BYTES;
                bulk_g2s(st,        aP + (size_t)(2 * kt) * A_KB_BYTES, 2 * A_KB_BYTES,
                         mb_full + s * 8);
                bulk_g2s(st + 8192, bP + (size_t)(2 * kt) * B_KB_BYTES, 2 * B_KB_BYTES,
                         mb_full + s * 8);
                if (++s == STAGES) { s = 0; e ^= 1; }
            }
        }
        return;
    }

    const int wm = wid & 1;      // M half (64 rows)
    const int wn = wid >> 1;     // N half (64 cols)

    uint32_t acc[4][8][2];
#pragma unroll
    for (int mi = 0; mi < 4; ++mi)
#pragma unroll
        for (int ni = 0; ni < 8; ++ni) { acc[mi][ni][0] = 0u; acc[mi][ni][1] = 0u; }

    const uint32_t aoff = lane * 16;
    const uint32_t boff = lane * 8;

    int s = 0, e = 0;
    for (int kt = 0; kt < NITER; ++kt) {
        MBAR_WAIT(mb_full + s * 8, e);
        const uint32_t stA = tiles + s * STAGE_BYTES;
        const uint32_t stB = stA + 8192;
#pragma unroll
        for (int s16 = 0; s16 < 2; ++s16) {
            uint32_t a[4][4], b[8][2];
#pragma unroll
            for (int mi = 0; mi < 4; ++mi) {
                const uint32_t ad = stA + (uint32_t)(s16 * 8 + wm * 4 + mi) * 512 + aoff;
                asm volatile("ld.shared.v4.b32 {%0,%1,%2,%3}, [%4];"
                    : "=r"(a[mi][0]), "=r"(a[mi][1]), "=r"(a[mi][2]), "=r"(a[mi][3])
                    : "r"(ad));
            }
#pragma unroll
            for (int ni = 0; ni < 8; ++ni) {
                const uint32_t bd = stB + (uint32_t)(s16 * 16 + wn * 8 + ni) * 256 + boff;
                asm volatile("ld.shared.v2.b32 {%0,%1}, [%2];"
                    : "=r"(b[ni][0]), "=r"(b[ni][1]) : "r"(bd));
            }
#pragma unroll
            for (int mi = 0; mi < 4; ++mi)
#pragma unroll
                for (int ni = 0; ni < 8; ++ni)
                    hmma16(acc[mi][ni], a[mi], b[ni]);
        }
        if (lane == 0) MBAR_ARRIVE(mb_empty + s * 8);
        if (++s == STAGES) { s = 0; e ^= 1; }
    }

    // ---- epilogue: clip, top-2 per (row, 32-col quarter); warp owns 2 quarters ----
    const int rowbase = blockIdx.y * BM + wm * 64;
#pragma unroll
    for (int mi = 0; mi < 4; ++mi) {
#pragma unroll
        for (int ih = 0; ih < 2; ++ih) {
            const int r = rowbase + mi * 16 + ih * 8 + (lane >> 2);
#pragma unroll
            for (int g4 = 0; g4 < 2; ++g4) {
                const int colbase = blockIdx.x * BN + wn * 64 + g4 * 32 + (lane & 3) * 2;
                unsigned long long k1 = 0ULL, k2 = 0ULL;
#pragma unroll
                for (int n4 = 0; n4 < 4; ++n4) {
                    const int ni = g4 * 4 + n4;
                    const __half2 hv = *(__half2*)&acc[mi][ni][ih];
                    const float s0 = fminf(fmaxf(__low2float(hv), 0.f), 1.f);
                    const float s1 = fminf(fmaxf(__high2float(hv), 0.f), 1.f);
                    const int c = colbase + n4 * 8;
                    unsigned long long key = enc_key(s0, c);
                    if (key > k1) { k2 = k1; k1 = key; }
                    else if (key > k2) { k2 = key; }
                    key = enc_key(s1, c + 1);
                    if (key > k1) { k2 = k1; k1 = key; }
                    else if (key > k2) { k2 = key; }
                }
#pragma unroll
                for (int m = 1; m <= 2; m <<= 1) {
                    const unsigned long long o1 = __shfl_xor_sync(0xffffffffu, k1, m);
                    const unsigned long long o2 = __shfl_xor_sync(0xffffffffu, k2, m);
                    if (o1 > k1) { k2 = (k1 > o2) ? k1 : o2; k1 = o1; }
                    else         { k2 = (k2 > o1) ? k2 : o1; }
                }
                if ((lane & 3) == 0) {
                    ulonglong2 kk; kk.x = k1; kk.y = k2;
                    *(ulonglong2*)&g_cands[(size_t)r * 256 + blockIdx.x * 8 +
                                           (wn * 2 + g4) * 2] = kk;
                }
            }
        }
    }
}

// ---------------- rescore (R12-identical) ----------------
__global__ void __launch_bounds__(256) rescore_kernel(
    const float* __restrict__ emb, const float* __restrict__ cen,
    float* __restrict__ out, int B_, int twoout) {
    __shared__ unsigned long long list[8][16];
    __shared__ int lcnt[8];

    const int w = threadIdx.x >> 5;
    const int lane = threadIdx.x & 31;
    const int row = blockIdx.x * 8 + w;
    if (row >= B_) return;

    unsigned long long k[8];
#pragma unroll
    for (int j = 0; j < 8; ++j)
        k[j] = g_cands[(size_t)row * 256 + j * 32 + lane];

    unsigned long long kmax = 0ULL;
#pragma unroll
    for (int j = 0; j < 8; ++j) if (k[j] > kmax) kmax = k[j];
#pragma unroll
    for (int m = 16; m >= 1; m >>= 1) {
        const unsigned long long o = __shfl_xor_sync(0xffffffffu, kmax, m);
        if (o > kmax) kmax = o;
    }
    const float smax = __uint_as_float((unsigned)(kmax >> 32));
    const float th = smax - DELTA;

    if (lane == 0) lcnt[w] = 0;
    __syncwarp();
#pragma unroll
    for (int j = 0; j < 8; ++j) {
        if (__uint_as_float((unsigned)(k[j] >> 32)) >= th) {
            const int pos = atomicAdd(&lcnt[w], 1);
            if (pos < 16) list[w][pos] = k[j];
        }
    }
    __syncwarp();
    const int n = min(lcnt[w], 16);

    float4 e[8];
    const float4* e4 = (const float4*)(emb + (size_t)row * D_DIM);
#pragma unroll
    for (int t = 0; t < 8; ++t) e[t] = e4[t * 32 + lane];
    const float einv = g_einv[row];

    unsigned long long bestk = 0ULL;
    for (int i = 0; i < n; ++i) {
        const unsigned col = 0xFFFFFFFFu - (unsigned)(list[w][i] & 0xFFFFFFFFu);
        const float4* c4 = (const float4*)(cen + (size_t)col * D_DIM);
        float d = 0.f;
#pragma unroll
        for (int t = 0; t < 8; ++t) {
            const float4 cv = c4[t * 32 + lane];
            d += e[t].x * cv.x + e[t].y * cv.y + e[t].z * cv.z + e[t].w * cv.w;
        }
#pragma unroll
        for (int m = 16; m >= 1; m >>= 1) d += __shfl_xor_sync(0xffffffffu, d, m);
        const float sim = fminf(fmaxf(d * einv * g_cinv[col], 0.f), 1.f);
        const unsigned long long key = enc_key(sim, (int)col);
        if (key > bestk) bestk = key;
    }

    if (lane == 0) {
        const float bsim = __uint_as_float((unsigned)(bestk >> 32));
        const unsigned bcol = 0xFFFFFFFFu - (unsigned)(bestk & 0xFFFFFFFFu);
        float nov = sqrtf(fmaxf(1.0f - bsim, 0.0f));
        out[row] = fminf(fmaxf(nov, 0.0f), 1.0f);
        if (twoout) out[B_ + row] = (float)bcol;
    }
}

// ---------------- launch ----------------
extern "C" void kernel_launch(void* const* d_in, const int* in_sizes, int n_in,
                              void* d_out, int out_size) {
    const float* emb = (const float*)d_in[0];
    const float* cen = (const float*)d_in[1];
    const int B_ = in_sizes[0] / D_DIM;   // 8192
    const int C_ = in_sizes[1] / D_DIM;   // 4096

    split_kernel<<<(B_ + C_) / 16, 512>>>(emb, cen, B_, C_);

    cudaFuncSetAttribute(gemm_kernel,
                         cudaFuncAttributeMaxDynamicSharedMemorySize, SMEM_DYN);
    dim3 grid(C_ / BN, B_ / BM);          // 32 x 64 = 2048 CTAs
    gemm_kernel<<<grid, 160, SMEM_DYN>>>();

    const int twoout = (out_size >= 2 * B_) ? 1 : 0;
    rescore_kernel<<<(B_ + 7) / 8, 256>>>(emb, cen, (float*)d_out, B_, twoout);
}

// round 16
// speedup vs baseline: 1.3232x; 1.0359x over previous
#include <cuda_runtime.h>
#include <cuda_fp16.h>
#include <cstdint>

#define D_DIM   1024
#define NKB     64            // 1024/16 k-blocks
#define NITER   32            // 1024/32
#define STAGES  4
#define BM      128
#define BN      128
#define NPA     64            // 8192/128 row panels
#define NPB     32            // 4096/128 col panels

#define A_KB_BYTES 4096
#define B_KB_BYTES 4096
#define STAGE_BYTES 16384
#define SMEM_DYN (1024 + STAGES * STAGE_BYTES)
#define DELTA 5e-3f

__device__ __align__(128) unsigned char g_A[(size_t)NPA * NKB * A_KB_BYTES]; // 16.8 MB
__device__ __align__(128) unsigned char g_B[(size_t)NPB * NKB * B_KB_BYTES]; // 8.4 MB
__device__ unsigned long long g_cands[(size_t)8192 * 256];                    // 16 MB
__device__ float g_einv[8192];
__device__ float g_cinv[4096];

struct __align__(8) H4 { __half2 a, b; };

// ---------------- PTX helpers ----------------
__device__ __forceinline__ uint32_t smem_u32(const void* p) {
    uint32_t a;
    asm("{ .reg .u64 t; cvta.to.shared.u64 t, %1; cvt.u32.u64 %0, t; }" : "=r"(a) : "l"(p));
    return a;
}
#define MBAR_INIT(a, n) \
    asm volatile("mbarrier.init.shared.b64 [%0], %1;" :: "r"(a), "r"((uint32_t)(n)) : "memory")
#define MBAR_ARRIVE(a) \
    asm volatile("mbarrier.arrive.shared.b64 _, [%0];" :: "r"(a) : "memory")
#define MBAR_EXPECT_TX(a, b) \
    asm volatile("mbarrier.arrive.expect_tx.shared.b64 _, [%0], %1;" :: "r"(a), "r"((uint32_t)(b)) : "memory")
#define MBAR_WAIT(a, ph) do {                                                      \
    uint32_t _m = (a), _p = (ph), _d;                                              \
    asm volatile("{ .reg .pred p; mbarrier.try_wait.parity.acquire.cta.shared::cta.b64 p, [%1], %2; selp.b32 %0,1,0,p; }" \
        : "=r"(_d) : "r"(_m), "r"(_p) : "memory");                                 \
    if (!_d) {                                                                     \
        asm volatile("{ .reg .pred P; L1_%=: mbarrier.try_wait.parity.acquire.cta.shared::cta.b64 P, [%0], %1, 0x989680; @P bra.uni L2_%=; bra.uni L1_%=; L2_%=: }" \
            :: "r"(_m), "r"(_p) : "memory");                                       \
    }                                                                              \
} while (0)

__device__ __forceinline__ void bulk_g2s(uint32_t dst, const void* src,
                                         uint32_t bytes, uint32_t mbar) {
    asm volatile("cp.async.bulk.shared::cluster.global.mbarrier::complete_tx::bytes [%0], [%1], %2, [%3];"
        :: "r"(dst), "l"(src), "r"(bytes), "r"(mbar) : "memory");
}
__device__ __forceinline__ void hmma16(uint32_t* d, const uint32_t* a, const uint32_t* b) {
    asm volatile(
        "mma.sync.aligned.m16n8k16.row.col.f16.f16.f16.f16 "
        "{%0,%1}, {%2,%3,%4,%5}, {%6,%7}, {%0,%1};"
        : "+r"(d[0]), "+r"(d[1])
        : "r"(a[0]), "r"(a[1]), "r"(a[2]), "r"(a[3]), "r"(b[0]), "r"(b[1]));
}
__device__ __forceinline__ unsigned long long enc_key(float sim, int col) {
    return ((unsigned long long)__float_as_uint(sim) << 32) |
           (unsigned long long)(0xFFFFFFFFu - (unsigned)col);
}
__device__ __forceinline__ float4 ldg_v4(const float4* p) {
    float4 v;
    asm volatile("ld.global.v4.f32 {%0,%1,%2,%3}, [%4];"
        : "=f"(v.x), "=f"(v.y), "=f"(v.z), "=f"(v.w) : "l"(p));
    return v;
}

// ---------------- split: two-pass (sumsq stream, then L2 re-load + convert) ----------------
__global__ void __launch_bounds__(512) split_kernel(const float* __restrict__ emb,
                                                    const float* __restrict__ cen,
                                                    int B_, int C_) {
    __shared__ __align__(16) unsigned char sh[16 * 2064];
    const int t = threadIdx.x;
    const int w = t >> 5;
    const int l = t & 31;

    const int nA = B_ >> 4;
    const bool isA = (int)blockIdx.x < nA;
    const int g = isA ? blockIdx.x : blockIdx.x - nA;
    const int row = g * 16 + w;
    const float4* p4 = (const float4*)((isA ? emb : cen) + (size_t)row * D_DIM);

    // pass 1: stream + sum of squares (values discarded -> short live ranges)
    float s = 0.f;
#pragma unroll
    for (int j = 0; j < 8; ++j) {
        const float4 v = p4[l + 32 * j];
        s += v.x * v.x + v.y * v.y + v.z * v.z + v.w * v.w;
    }
#pragma unroll
    for (int m = 16; m >= 1; m >>= 1) s += __shfl_xor_sync(0xffffffffu, s, m);
    const float inv = 1.0f / fmaxf(sqrtf(s), 1e-12f);
    if (l == 0) {
        if (isA) g_einv[row] = inv;
        else     g_cinv[row] = inv;
    }

    // pass 2: re-load (L2 hit; asm volatile prevents CSE with pass 1), convert, stage
#pragma unroll
    for (int j = 0; j < 8; ++j) {
        const float4 v = ldg_v4(p4 + l + 32 * j);
        H4 hv;
        hv.a = __floats2half2_rn(v.x * inv, v.y * inv);
        hv.b = __floats2half2_rn(v.z * inv, v.w * inv);
        *(H4*)(sh + w * 2064 + l * 8 + 256 * j) = hv;
    }
    __syncthreads();

    if (isA) {
        const int pnl = g >> 3, mblk = g & 7;
        unsigned char* base = g_A + (size_t)pnl * NKB * A_KB_BYTES + mblk * 512 + l * 16;
#pragma unroll
        for (int it = 0; it < 4; ++it) {
            const int kb = it * 16 + w;
            uint32_t v[4];
#pragma unroll
            for (int r = 0; r < 4; ++r) {
                const int i  = (l >> 2) + 8 * (r & 1);
                const int kk = kb * 16 + (l & 3) * 2 + 8 * (r >> 1);
                v[r] = *(const uint32_t*)(sh + i * 2064 + kk * 2);
            }
            *(uint4*)(base + (size_t)kb * A_KB_BYTES) = make_uint4(v[0], v[1], v[2], v[3]);
        }
    } else {
        const int pnl = g >> 3;
        const int nb_base = (g & 7) * 2;
        unsigned char* base = g_B + (size_t)pnl * NKB * B_KB_BYTES + l * 8;
#pragma unroll
        for (int it = 0; it < 8; ++it) {
            const int ci = it * 16 + w;
            const int kb = ci >> 1, nloc = ci & 1;
            uint32_t v[2];
#pragma unroll
            for (int s2 = 0; s2 < 2; ++s2) {
                const int i  = nloc * 8 + (l >> 2);
                const int kk = kb * 16 + (l & 3) * 2 + 8 * s2;
                v[s2] = *(const uint32_t*)(sh + i * 2064 + kk * 2);
            }
            *(uint2*)(base + (size_t)kb * B_KB_BYTES + (nb_base + nloc) * 256) =
                make_uint2(v[0], v[1]);
        }
    }
}

// ---------------- HMMA GEMM (R12-identical): 4 warps x (64x64), 3 CTAs/SM ----------------
__global__ void __launch_bounds__(160, 3) gemm_kernel() {
    extern __shared__ __align__(16) unsigned char smem[];
    const uint32_t sbase = smem_u32(smem);
    const int tid = threadIdx.x;
    const int wid = tid >> 5;
    const int lane = tid & 31;

    const uint32_t mb_full  = sbase;
    const uint32_t mb_empty = sbase + 64;
    const uint32_t tiles    = sbase + 1024;

    if (tid == 0) {
#pragma unroll
        for (int s = 0; s < STAGES; ++s) {
            MBAR_INIT(mb_full + s * 8, 1);
            MBAR_INIT(mb_empty + s * 8, 4);     // 4 consumer warps
        }
    }
    __syncthreads();

    if (wid == 4) {
        if (lane == 0) {
            const unsigned char* aP = g_A + (size_t)blockIdx.y * NKB * A_KB_BYTES;
            const unsigned char* bP = g_B + (size_t)blockIdx.x * NKB * B_KB_BYTES;
            for (int kt = 0; kt < NITER; ++kt) {
                const int s = kt & (STAGES - 1);
                MBAR_WAIT(mb_empty + s * 8, 1u ^ ((kt >> 2) & 1));
                MBAR_EXPECT_TX(mb_full + s * 8, STAGE_BYTES);
                const uint32_t st = tiles + s * STAGE_BYTES;
                bulk_g2s(st,        aP + (size_t)(2 * kt) * A_KB_BYTES, 2 * A_KB_BYTES,
                         mb_full + s * 8);
                bulk_g2s(st + 8192, bP + (size_t)(2 * kt) * B_KB_BYTES, 2 * B_KB_BYTES,
                         mb_full + s * 8);
            }
        }
        return;
    }

    const int wm = wid & 1;      // M half (64 rows)
    const int wn = wid >> 1;     // N half (64 cols)

    uint32_t acc[4][8][2];
#pragma unroll
    for (int mi = 0; mi < 4; ++mi)
#pragma unroll
        for (int ni = 0; ni < 8; ++ni) { acc[mi][ni][0] = 0u; acc[mi][ni][1] = 0u; }

    const uint32_t aoff = lane * 16;
    const uint32_t boff = lane * 8;

    for (int kt = 0; kt < NITER; ++kt) {
        const int s = kt & (STAGES - 1);
        MBAR_WAIT(mb_full + s * 8, (kt >> 2) & 1);
        const uint32_t stA = tiles + s * STAGE_BYTES;
        const uint32_t stB = stA + 8192;
#pragma unroll
        for (int s16 = 0; s16 < 2; ++s16) {
            uint32_t a[4][4], b[8][2];
#pragma unroll
            for (int mi = 0; mi < 4; ++mi) {
                const uint32_t ad = stA + (uint32_t)(s16 * 8 + wm * 4 + mi) * 512 + aoff;
                asm volatile("ld.shared.v4.b32 {%0,%1,%2,%3}, [%4];"
                    : "=r"(a[mi][0]), "=r"(a[mi][1]), "=r"(a[mi][2]), "=r"(a[mi][3])
                    : "r"(ad));
            }
#pragma unroll
            for (int ni = 0; ni < 8; ++ni) {
                const uint32_t bd = stB + (uint32_t)(s16 * 16 + wn * 8 + ni) * 256 + boff;
                asm volatile("ld.shared.v2.b32 {%0,%1}, [%2];"
                    : "=r"(b[ni][0]), "=r"(b[ni][1]) : "r"(bd));
            }
#pragma unroll
            for (int mi = 0; mi < 4; ++mi)
#pragma unroll
                for (int ni = 0; ni < 8; ++ni)
                    hmma16(acc[mi][ni], a[mi], b[ni]);
        }
        if (lane == 0) MBAR_ARRIVE(mb_empty + s * 8);
    }

    // ---- epilogue: clip, top-2 per (row, 32-col quarter); warp owns 2 quarters ----
    const int rowbase = blockIdx.y * BM + wm * 64;
#pragma unroll
    for (int mi = 0; mi < 4; ++mi) {
#pragma unroll
        for (int ih = 0; ih < 2; ++ih) {
            const int r = rowbase + mi * 16 + ih * 8 + (lane >> 2);
#pragma unroll
            for (int g4 = 0; g4 < 2; ++g4) {
                const int colbase = blockIdx.x * BN + wn * 64 + g4 * 32 + (lane & 3) * 2;
                unsigned long long k1 = 0ULL, k2 = 0ULL;
#pragma unroll
                for (int n4 = 0; n4 < 4; ++n4) {
                    const int ni = g4 * 4 + n4;
                    const __half2 hv = *(__half2*)&acc[mi][ni][ih];
                    const float s0 = fminf(fmaxf(__low2float(hv), 0.f), 1.f);
                    const float s1 = fminf(fmaxf(__high2float(hv), 0.f), 1.f);
                    const int c = colbase + n4 * 8;
                    unsigned long long key = enc_key(s0, c);
                    if (key > k1) { k2 = k1; k1 = key; }
                    else if (key > k2) { k2 = key; }
                    key = enc_key(s1, c + 1);
                    if (key > k1) { k2 = k1; k1 = key; }
                    else if (key > k2) { k2 = key; }
                }
#pragma unroll
                for (int m = 1; m <= 2; m <<= 1) {
                    const unsigned long long o1 = __shfl_xor_sync(0xffffffffu, k1, m);
                    const unsigned long long o2 = __shfl_xor_sync(0xffffffffu, k2, m);
                    if (o1 > k1) { k2 = (k1 > o2) ? k1 : o2; k1 = o1; }
                    else         { k2 = (k2 > o1) ? k2 : o1; }
                }
                if ((lane & 3) == 0) {
                    ulonglong2 kk; kk.x = k1; kk.y = k2;
                    *(ulonglong2*)&g_cands[(size_t)r * 256 + blockIdx.x * 8 +
                                           (wn * 2 + g4) * 2] = kk;
                }
            }
        }
    }
}

// ---------------- rescore: vectorized candidate loads + exact fp32 rescoring ----------------
__global__ void __launch_bounds__(256) rescore_kernel(
    const float* __restrict__ emb, const float* __restrict__ cen,
    float* __restrict__ out, int B_, int twoout) {
    __shared__ unsigned long long list[8][16];
    __shared__ int lcnt[8];

    const int w = threadIdx.x >> 5;
    const int lane = threadIdx.x & 31;
    const int row = blockIdx.x * 8 + w;
    if (row >= B_) return;

    // per-lane 64B contiguous chunk (key set identical; order irrelevant)
    unsigned long long k[8];
    {
        const ulonglong2* base =
            (const ulonglong2*)&g_cands[(size_t)row * 256 + lane * 8];
#pragma unroll
        for (int q = 0; q < 4; ++q) {
            const ulonglong2 v = base[q];
            k[q * 2] = v.x; k[q * 2 + 1] = v.y;
        }
    }

    unsigned long long kmax = 0ULL;
#pragma unroll
    for (int j = 0; j < 8; ++j) if (k[j] > kmax) kmax = k[j];
#pragma unroll
    for (int m = 16; m >= 1; m >>= 1) {
        const unsigned long long o = __shfl_xor_sync(0xffffffffu, kmax, m);
        if (o > kmax) kmax = o;
    }
    const float smax = __uint_as_float((unsigned)(kmax >> 32));
    const float th = smax - DELTA;

    if (lane == 0) lcnt[w] = 0;
    __syncwarp();
#pragma unroll
    for (int j = 0; j < 8; ++j) {
        if (__uint_as_float((unsigned)(k[j] >> 32)) >= th) {
            const int pos = atomicAdd(&lcnt[w], 1);
            if (pos < 16) list[w][pos] = k[j];
        }
    }
    __syncwarp();
    const int n = min(lcnt[w], 16);

    float4 e[8];
    const float4* e4 = (const float4*)(emb + (size_t)row * D_DIM);
#pragma unroll
    for (int t = 0; t < 8; ++t) e[t] = e4[t * 32 + lane];
    const float einv = g_einv[row];

    unsigned long long bestk = 0ULL;
    for (int i = 0; i < n; ++i) {
        const unsigned col = 0xFFFFFFFFu - (unsigned)(list[w][i] & 0xFFFFFFFFu);
        const float4* c4 = (const float4*)(cen + (size_t)col * D_DIM);
        float d = 0.f;
#pragma unroll
        for (int t = 0; t < 8; ++t) {
            const float4 cv = c4[t * 32 + lane];
            d += e[t].x * cv.x + e[t].y * cv.y + e[t].z * cv.z + e[t].w * cv.w;
        }
#pragma unroll
        for (int m = 16; m >= 1; m >>= 1) d += __shfl_xor_sync(0xffffffffu, d, m);
        const float sim = fminf(fmaxf(d * einv * g_cinv[col], 0.f), 1.f);
        const unsigned long long key = enc_key(sim, (int)col);
        if (key > bestk) bestk = key;
    }

    if (lane == 0) {
        const float bsim = __uint_as_float((unsigned)(bestk >> 32));
        const unsigned bcol = 0xFFFFFFFFu - (unsigned)(bestk & 0xFFFFFFFFu);
        float nov = sqrtf(fmaxf(1.0f - bsim, 0.0f));
        out[row] = fminf(fmaxf(nov, 0.0f), 1.0f);
        if (twoout) out[B_ + row] = (float)bcol;
    }
}

// ---------------- launch ----------------
extern "C" void kernel_launch(void* const* d_in, const int* in_sizes, int n_in,
                              void* d_out, int out_size) {
    const float* emb = (const float*)d_in[0];
    const float* cen = (const float*)d_in[1];
    const int B_ = in_sizes[0] / D_DIM;   // 8192
    const int C_ = in_sizes[1] / D_DIM;   // 4096

    split_kernel<<<(B_ + C_) / 16, 512>>>(emb, cen, B_, C_);

    cudaFuncSetAttribute(gemm_kernel,
                         cudaFuncAttributeMaxDynamicSharedMemorySize, SMEM_DYN);
    dim3 grid(C_ / BN, B_ / BM);          // 32 x 64 = 2048 CTAs
    gemm_kernel<<<grid, 160, SMEM_DYN>>>();

    const int twoout = (out_size >= 2 * B_) ? 1 : 0;
    rescore_kernel<<<(B_ + 7) / 8, 256>>>(emb, cen, (float*)d_out, B_, twoout);
}

// round 17
// speedup vs baseline: 1.3389x; 1.0119x over previous
#include <cuda_runtime.h>
#include <cuda_fp16.h>
#include <cstdint>

#define D_DIM   1024
#define NKB     64            // 1024/16 k-blocks
#define NITER   32            // 1024/32
#define STAGES  4
#define BM      128
#define BN      128
#define NPA     64            // 8192/128 row panels
#define NPB     32            // 4096/128 col panels
#define NTILES  2048
#define GRIDW   1776          // 2048 - 272; bids < 272 take 2 tiles

#define A_KB_BYTES 4096
#define B_KB_BYTES 4096
#define STAGE_BYTES 16384
#define SMEM_DYN (1024 + STAGES * STAGE_BYTES)
#define DELTA 5e-3f

__device__ __align__(128) unsigned char g_A[(size_t)NPA * NKB * A_KB_BYTES]; // 16.8 MB
__device__ __align__(128) unsigned char g_B[(size_t)NPB * NKB * B_KB_BYTES]; // 8.4 MB
__device__ unsigned long long g_cands[(size_t)8192 * 256];                    // 16 MB
__device__ float g_einv[8192];
__device__ float g_cinv[4096];

struct __align__(8) H4 { __half2 a, b; };

// ---------------- PTX helpers ----------------
__device__ __forceinline__ uint32_t smem_u32(const void* p) {
    uint32_t a;
    asm("{ .reg .u64 t; cvta.to.shared.u64 t, %1; cvt.u32.u64 %0, t; }" : "=r"(a) : "l"(p));
    return a;
}
#define MBAR_INIT(a, n) \
    asm volatile("mbarrier.init.shared.b64 [%0], %1;" :: "r"(a), "r"((uint32_t)(n)) : "memory")
#define MBAR_ARRIVE(a) \
    asm volatile("mbarrier.arrive.shared.b64 _, [%0];" :: "r"(a) : "memory")
#define MBAR_EXPECT_TX(a, b) \
    asm volatile("mbarrier.arrive.expect_tx.shared.b64 _, [%0], %1;" :: "r"(a), "r"((uint32_t)(b)) : "memory")
#define MBAR_WAIT(a, ph) do {                                                      \
    uint32_t _m = (a), _p = (ph), _d;                                              \
    asm volatile("{ .reg .pred p; mbarrier.try_wait.parity.acquire.cta.shared::cta.b64 p, [%1], %2; selp.b32 %0,1,0,p; }" \
        : "=r"(_d) : "r"(_m), "r"(_p) : "memory");                                 \
    if (!_d) {                                                                     \
        asm volatile("{ .reg .pred P; L1_%=: mbarrier.try_wait.parity.acquire.cta.shared::cta.b64 P, [%0], %1, 0x989680; @P bra.uni L2_%=; bra.uni L1_%=; L2_%=: }" \
            :: "r"(_m), "r"(_p) : "memory");                                       \
    }                                                                              \
} while (0)

__device__ __forceinline__ void bulk_g2s(uint32_t dst, const void* src,
                                         uint32_t bytes, uint32_t mbar) {
    asm volatile("cp.async.bulk.shared::cluster.global.mbarrier::complete_tx::bytes [%0], [%1], %2, [%3];"
        :: "r"(dst), "l"(src), "r"(bytes), "r"(mbar) : "memory");
}
__device__ __forceinline__ void hmma16(uint32_t* d, const uint32_t* a, const uint32_t* b) {
    asm volatile(
        "mma.sync.aligned.m16n8k16.row.col.f16.f16.f16.f16 "
        "{%0,%1}, {%2,%3,%4,%5}, {%6,%7}, {%0,%1};"
        : "+r"(d[0]), "+r"(d[1])
        : "r"(a[0]), "r"(a[1]), "r"(a[2]), "r"(a[3]), "r"(b[0]), "r"(b[1]));
}
__device__ __forceinline__ unsigned long long enc_key(float sim, int col) {
    return ((unsigned long long)__float_as_uint(sim) << 32) |
           (unsigned long long)(0xFFFFFFFFu - (unsigned)col);
}

// ---------------- split (R12-identical) ----------------
__global__ void __launch_bounds__(512) split_kernel(const float* __restrict__ emb,
                                                    const float* __restrict__ cen,
                                                    int B_, int C_) {
    __shared__ __align__(16) unsigned char sh[16 * 2064];
    const int t = threadIdx.x;
    const int w = t >> 5;
    const int l = t & 31;

    const int nA = B_ >> 4;
    const bool isA = (int)blockIdx.x < nA;
    const int g = isA ? blockIdx.x : blockIdx.x - nA;
    const int row = g * 16 + w;
    const float* p = (isA ? emb : cen) + (size_t)row * D_DIM;

    float4 f[8];
    float s = 0.f;
#pragma unroll
    for (int j = 0; j < 8; ++j) {
        f[j] = ((const float4*)p)[l + 32 * j];
        s += f[j].x * f[j].x + f[j].y * f[j].y + f[j].z * f[j].z + f[j].w * f[j].w;
    }
#pragma unroll
    for (int m = 16; m >= 1; m >>= 1) s += __shfl_xor_sync(0xffffffffu, s, m);
    const float inv = 1.0f / fmaxf(sqrtf(s), 1e-12f);
    if (l == 0) {
        if (isA) g_einv[row] = inv;
        else     g_cinv[row] = inv;
    }

#pragma unroll
    for (int j = 0; j < 8; ++j) {
        H4 hv;
        hv.a = __floats2half2_rn(f[j].x * inv, f[j].y * inv);
        hv.b = __floats2half2_rn(f[j].z * inv, f[j].w * inv);
        *(H4*)(sh + w * 2064 + l * 8 + 256 * j) = hv;
    }
    __syncthreads();

    if (isA) {
        const int pnl = g >> 3, mblk = g & 7;
        unsigned char* base = g_A + (size_t)pnl * NKB * A_KB_BYTES + mblk * 512 + l * 16;
#pragma unroll
        for (int it = 0; it < 4; ++it) {
            const int kb = it * 16 + w;
            uint32_t v[4];
#pragma unroll
            for (int r = 0; r < 4; ++r) {
                const int i  = (l >> 2) + 8 * (r & 1);
                const int kk = kb * 16 + (l & 3) * 2 + 8 * (r >> 1);
                v[r] = *(const uint32_t*)(sh + i * 2064 + kk * 2);
            }
            *(uint4*)(base + (size_t)kb * A_KB_BYTES) = make_uint4(v[0], v[1], v[2], v[3]);
        }
    } else {
        const int pnl = g >> 3;
        const int nb_base = (g & 7) * 2;
        unsigned char* base = g_B + (size_t)pnl * NKB * B_KB_BYTES + l * 8;
#pragma unroll
        for (int it = 0; it < 8; ++it) {
            const int ci = it * 16 + w;
            const int kb = ci >> 1, nloc = ci & 1;
            uint32_t v[2];
#pragma unroll
            for (int s2 = 0; s2 < 2; ++s2) {
                const int i  = nloc * 8 + (l >> 2);
                const int kk = kb * 16 + (l & 3) * 2 + 8 * s2;
                v[s2] = *(const uint32_t*)(sh + i * 2064 + kk * 2);
            }
            *(uint2*)(base + (size_t)kb * B_KB_BYTES + (nb_base + nloc) * 256) =
                make_uint2(v[0], v[1]);
        }
    }
}

// ---------------- HMMA GEMM: R12 internals, max-2-tile balanced persistence ----------------
__global__ void __launch_bounds__(160, 3) gemm_kernel() {
    extern __shared__ __align__(16) unsigned char smem[];
    const uint32_t sbase = smem_u32(smem);
    const int tid = threadIdx.x;
    const int wid = tid >> 5;
    const int lane = tid & 31;
    const int bid = blockIdx.x;

    const uint32_t mb_full  = sbase;
    const uint32_t mb_empty = sbase + 64;
    const uint32_t tiles    = sbase + 1024;

    if (tid == 0) {
#pragma unroll
        for (int s = 0; s < STAGES; ++s) {
            MBAR_INIT(mb_full + s * 8, 1);
            MBAR_INIT(mb_empty + s * 8, 4);     // 4 consumer warps
        }
    }
    __syncthreads();

    if (wid == 4) {
        // ---- producer: continuous pipeline across 1-2 tiles ----
        if (lane == 0) {
            int it = 0;
            for (int t = bid; t < NTILES; t += GRIDW) {
                const unsigned char* aP = g_A + (size_t)(t >> 5) * NKB * A_KB_BYTES;
                const unsigned char* bP = g_B + (size_t)(t & 31) * NKB * B_KB_BYTES;
                for (int kt = 0; kt < NITER; ++kt, ++it) {
                    const int s = it & (STAGES - 1);
                    MBAR_WAIT(mb_empty + s * 8, 1u ^ ((it >> 2) & 1));
                    MBAR_EXPECT_TX(mb_full + s * 8, STAGE_BYTES);
                    const uint32_t st = tiles + s * STAGE_BYTES;
                    bulk_g2s(st,        aP + (size_t)(2 * kt) * A_KB_BYTES,
                             2 * A_KB_BYTES, mb_full + s * 8);
                    bulk_g2s(st + 8192, bP + (size_t)(2 * kt) * B_KB_BYTES,
                             2 * B_KB_BYTES, mb_full + s * 8);
                }
            }
        }
        return;
    }

    const int wm = wid & 1;      // M half (64 rows)
    const int wn = wid >> 1;     // N half (64 cols)
    const uint32_t aoff = lane * 16;
    const uint32_t boff = lane * 8;

    int it = 0;
    for (int t = bid; t < NTILES; t += GRIDW) {
        uint32_t acc[4][8][2];
#pragma unroll
        for (int mi = 0; mi < 4; ++mi)
#pragma unroll
            for (int ni = 0; ni < 8; ++ni) { acc[mi][ni][0] = 0u; acc[mi][ni][1] = 0u; }

        for (int kt = 0; kt < NITER; ++kt, ++it) {
            const int s = it & (STAGES - 1);
            MBAR_WAIT(mb_full + s * 8, (it >> 2) & 1);
            const uint32_t stA = tiles + s * STAGE_BYTES;
            const uint32_t stB = stA + 8192;
#pragma unroll
            for (int s16 = 0; s16 < 2; ++s16) {
                uint32_t a[4][4], b[8][2];
#pragma unroll
                for (int mi = 0; mi < 4; ++mi) {
                    const uint32_t ad = stA + (uint32_t)(s16 * 8 + wm * 4 + mi) * 512 + aoff;
                    asm volatile("ld.shared.v4.b32 {%0,%1,%2,%3}, [%4];"
                        : "=r"(a[mi][0]), "=r"(a[mi][1]), "=r"(a[mi][2]), "=r"(a[mi][3])
                        : "r"(ad));
                }
#pragma unroll
                for (int ni = 0; ni < 8; ++ni) {
                    const uint32_t bd = stB + (uint32_t)(s16 * 16 + wn * 8 + ni) * 256 + boff;
                    asm volatile("ld.shared.v2.b32 {%0,%1}, [%2];"
                        : "=r"(b[ni][0]), "=r"(b[ni][1]) : "r"(bd));
                }
#pragma unroll
                for (int mi = 0; mi < 4; ++mi)
#pragma unroll
                    for (int ni = 0; ni < 8; ++ni)
                        hmma16(acc[mi][ni], a[mi], b[ni]);
            }
            if (lane == 0) MBAR_ARRIVE(mb_empty + s * 8);
        }

        // ---- epilogue for this tile ----
        const int by = t >> 5, bx = t & 31;
        const int rowbase = by * BM + wm * 64;
#pragma unroll
        for (int mi = 0; mi < 4; ++mi) {
#pragma unroll
            for (int ih = 0; ih < 2; ++ih) {
                const int r = rowbase + mi * 16 + ih * 8 + (lane >> 2);
#pragma unroll
                for (int g4 = 0; g4 < 2; ++g4) {
                    const int colbase = bx * BN + wn * 64 + g4 * 32 + (lane & 3) * 2;
                    unsigned long long k1 = 0ULL, k2 = 0ULL;
#pragma unroll
                    for (int n4 = 0; n4 < 4; ++n4) {
                        const int ni = g4 * 4 + n4;
                        const __half2 hv = *(__half2*)&acc[mi][ni][ih];
                        const float s0 = fminf(fmaxf(__low2float(hv), 0.f), 1.f);
                        const float s1 = fminf(fmaxf(__high2float(hv), 0.f), 1.f);
                        const int c = colbase + n4 * 8;
                        unsigned long long key = enc_key(s0, c);
                        if (key > k1) { k2 = k1; k1 = key; }
                        else if (key > k2) { k2 = key; }
                        key = enc_key(s1, c + 1);
                        if (key > k1) { k2 = k1; k1 = key; }
                        else if (key > k2) { k2 = key; }
                    }
#pragma unroll
                    for (int m = 1; m <= 2; m <<= 1) {
                        const unsigned long long o1 = __shfl_xor_sync(0xffffffffu, k1, m);
                        const unsigned long long o2 = __shfl_xor_sync(0xffffffffu, k2, m);
                        if (o1 > k1) { k2 = (k1 > o2) ? k1 : o2; k1 = o1; }
                        else         { k2 = (k2 > o1) ? k2 : o1; }
                    }
                    if ((lane & 3) == 0) {
                        ulonglong2 kk; kk.x = k1; kk.y = k2;
                        *(ulonglong2*)&g_cands[(size_t)r * 256 + bx * 8 +
                                               (wn * 2 + g4) * 2] = kk;
                    }
                }
            }
        }
    }
}

// ---------------- rescore: R12 + vectorized candidate loads ----------------
__global__ void __launch_bounds__(256) rescore_kernel(
    const float* __restrict__ emb, const float* __restrict__ cen,
    float* __restrict__ out, int B_, int twoout) {
    __shared__ unsigned long long list[8][16];
    __shared__ int lcnt[8];

    const int w = threadIdx.x >> 5;
    const int lane = threadIdx.x & 31;
    const int row = blockIdx.x * 8 + w;
    if (row >= B_) return;

    unsigned long long k[8];
    {
        const ulonglong2* base =
            (const ulonglong2*)&g_cands[(size_t)row * 256 + lane * 8];
#pragma unroll
        for (int q = 0; q < 4; ++q) {
            const ulonglong2 v = base[q];
            k[q * 2] = v.x; k[q * 2 + 1] = v.y;
        }
    }

    unsigned long long kmax = 0ULL;
#pragma unroll
    for (int j = 0; j < 8; ++j) if (k[j] > kmax) kmax = k[j];
#pragma unroll
    for (int m = 16; m >= 1; m >>= 1) {
        const unsigned long long o = __shfl_xor_sync(0xffffffffu, kmax, m);
        if (o > kmax) kmax = o;
    }
    const float smax = __uint_as_float((unsigned)(kmax >> 32));
    const float th = smax - DELTA;

    if (lane == 0) lcnt[w] = 0;
    __syncwarp();
#pragma unroll
    for (int j = 0; j < 8; ++j) {
        if (__uint_as_float((unsigned)(k[j] >> 32)) >= th) {
            const int pos = atomicAdd(&lcnt[w], 1);
            if (pos < 16) list[w][pos] = k[j];
        }
    }
    __syncwarp();
    const int n = min(lcnt[w], 16);

    float4 e[8];
    const float4* e4 = (const float4*)(emb + (size_t)row * D_DIM);
#pragma unroll
    for (int t = 0; t < 8; ++t) e[t] = e4[t * 32 + lane];
    const float einv = g_einv[row];

    unsigned long long bestk = 0ULL;
    for (int i = 0; i < n; ++i) {
        const unsigned col = 0xFFFFFFFFu - (unsigned)(list[w][i] & 0xFFFFFFFFu);
        const float4* c4 = (const float4*)(cen + (size_t)col * D_DIM);
        float d = 0.f;
#pragma unroll
        for (int t = 0; t < 8; ++t) {
            const float4 cv = c4[t * 32 + lane];
            d += e[t].x * cv.x + e[t].y * cv.y + e[t].z * cv.z + e[t].w * cv.w;
        }
#pragma unroll
        for (int m = 16; m >= 1; m >>= 1) d += __shfl_xor_sync(0xffffffffu, d, m);
        const float sim = fminf(fmaxf(d * einv * g_cinv[col], 0.f), 1.f);
        const unsigned long long key = enc_key(sim, (int)col);
        if (key > bestk) bestk = key;
    }

    if (lane == 0) {
        const float bsim = __uint_as_float((unsigned)(bestk >> 32));
        const unsigned bcol = 0xFFFFFFFFu - (unsigned)(bestk & 0xFFFFFFFFu);
        float nov = sqrtf(fmaxf(1.0f - bsim, 0.0f));
        out[row] = fminf(fmaxf(nov, 0.0f), 1.0f);
        if (twoout) out[B_ + row] = (float)bcol;
    }
}

// ---------------- launch ----------------
extern "C" void kernel_launch(void* const* d_in, const int* in_sizes, int n_in,
                              void* d_out, int out_size) {
    const float* emb = (const float*)d_in[0];
    const float* cen = (const float*)d_in[1];
    const int B_ = in_sizes[0] / D_DIM;   // 8192
    const int C_ = in_sizes[1] / D_DIM;   // 4096

    split_kernel<<<(B_ + C_) / 16, 512>>>(emb, cen, B_, C_);

    cudaFuncSetAttribute(gemm_kernel,
                         cudaFuncAttributeMaxDynamicSharedMemorySize, SMEM_DYN);
    gemm_kernel<<<GRIDW, 160, SMEM_DYN>>>();

    const int twoout = (out_size >= 2 * B_) ? 1 : 0;
    rescore_kernel<<<(B_ + 7) / 8, 256>>>(emb, cen, (float*)d_out, B_, twoout);
}